// round 14
// baseline (speedup 1.0000x reference)
#include <cuda_runtime.h>
#include <cstdint>
#include <math_constants.h>

// Problem constants
#define BB   16
#define PP   196
#define DD   512
#define LL   32
#define HID  512
#define AA   512
#define MM   (BB*LL)
#define PT   7            // pixels per scores tile
#define PCN  4            // ctx p-chunks
#define PCL  49           // pixels per ctx chunk (4*49 = 196)

// ---------------- scratch (device globals; no allocation allowed) -----------
__device__ __align__(16) float g_hlin[MM * AA];
__device__ __align__(16) float g_scores[MM * PP];
__device__ __align__(16) float g_attnT[BB * PP * LL];   // [b][p][l]
__device__ __align__(16) float g_ctx[MM * DD];
__device__ __align__(16) float g_part[PCN * MM * DD];   // ctx partials (4 MB)

// ---------------------------------------------------------------------------
// NT SGEMM  out[m,n] = sum_k X[m,k] * Wt[n,k] + bias[n]
//   MODE 0: X = Xp param, out = g_hlin
//   MODE 1: X = g_ctx, out = outp * mul
// BM=64, BN=32, BK=32, 256 threads (16x16). K-major double-buffered smem,
// register-prefetch pipeline. grid = (16, 8) = 128 blocks.
// ---------------------------------------------------------------------------
template<int MODE>
__global__ __launch_bounds__(256) void gemm_nt_kernel(
    const float* __restrict__ Xp, const float* __restrict__ Wt,
    const float* __restrict__ bias, const float* __restrict__ mul,
    float* __restrict__ outp)
{
    __shared__ __align__(16) float Xs[2][32][68];
    __shared__ __align__(16) float Ws[2][32][34];

    const int tid = threadIdx.x;
    const int tx = tid & 15;         // N
    const int ty = tid >> 4;         // M
    const int bm = blockIdx.y * 64;
    const int bn = blockIdx.x * 32;

    float acc[4][2];
#pragma unroll
    for (int i = 0; i < 4; ++i)
#pragma unroll
        for (int j = 0; j < 2; ++j) acc[i][j] = 0.f;

    const int xrow = tid >> 2;             // 0..63
    const int xko  = (tid & 3) * 4;        // 0,4,8,12 ; second vec at +16
    const int wrow = tid >> 3;             // 0..31
    const int wko  = (tid & 7) * 4;        // 0..28

    const float* X = (MODE == 0) ? Xp : g_ctx;
    const float* xg0 = X + (size_t)(bm + xrow) * 512 + xko;
    const float* wg  = Wt + (size_t)(bn + wrow) * 512 + wko;

    float4 xv0 = *(const float4*)(xg0);
    float4 xv1 = *(const float4*)(xg0 + 16);
    float4 wv  = *(const float4*)(wg);

    Xs[0][xko + 0][xrow] = xv0.x; Xs[0][xko + 1][xrow] = xv0.y;
    Xs[0][xko + 2][xrow] = xv0.z; Xs[0][xko + 3][xrow] = xv0.w;
    Xs[0][xko + 16][xrow] = xv1.x; Xs[0][xko + 17][xrow] = xv1.y;
    Xs[0][xko + 18][xrow] = xv1.z; Xs[0][xko + 19][xrow] = xv1.w;
    Ws[0][wko + 0][wrow] = wv.x; Ws[0][wko + 1][wrow] = wv.y;
    Ws[0][wko + 2][wrow] = wv.z; Ws[0][wko + 3][wrow] = wv.w;
    __syncthreads();

#pragma unroll 1
    for (int c = 0; c < 16; ++c) {
        if (c < 15) {
            const float* xg = xg0 + (c + 1) * 32;
            xv0 = *(const float4*)(xg);
            xv1 = *(const float4*)(xg + 16);
            wv  = *(const float4*)(wg + (c + 1) * 32);
        }

        const int cur = c & 1;
#pragma unroll
        for (int kk = 0; kk < 32; ++kk) {
            float4 a = *(const float4*)&Xs[cur][kk][ty * 4];
            float2 bv = *(const float2*)&Ws[cur][kk][tx * 2];
            acc[0][0] = fmaf(a.x, bv.x, acc[0][0]); acc[0][1] = fmaf(a.x, bv.y, acc[0][1]);
            acc[1][0] = fmaf(a.y, bv.x, acc[1][0]); acc[1][1] = fmaf(a.y, bv.y, acc[1][1]);
            acc[2][0] = fmaf(a.z, bv.x, acc[2][0]); acc[2][1] = fmaf(a.z, bv.y, acc[2][1]);
            acc[3][0] = fmaf(a.w, bv.x, acc[3][0]); acc[3][1] = fmaf(a.w, bv.y, acc[3][1]);
        }

        if (c < 15) {
            const int nxt = cur ^ 1;
            Xs[nxt][xko + 0][xrow] = xv0.x; Xs[nxt][xko + 1][xrow] = xv0.y;
            Xs[nxt][xko + 2][xrow] = xv0.z; Xs[nxt][xko + 3][xrow] = xv0.w;
            Xs[nxt][xko + 16][xrow] = xv1.x; Xs[nxt][xko + 17][xrow] = xv1.y;
            Xs[nxt][xko + 18][xrow] = xv1.z; Xs[nxt][xko + 19][xrow] = xv1.w;
            Ws[nxt][wko + 0][wrow] = wv.x; Ws[nxt][wko + 1][wrow] = wv.y;
            Ws[nxt][wko + 2][wrow] = wv.z; Ws[nxt][wko + 3][wrow] = wv.w;
            __syncthreads();
        }
    }

    float* out = (MODE == 0) ? g_hlin : outp;
#pragma unroll
    for (int i = 0; i < 4; ++i) {
        int r = bm + ty * 4 + i;
#pragma unroll
        for (int j = 0; j < 2; ++j) {
            int cc = bn + tx * 2 + j;
            float v = acc[i][j] + bias[cc];
            if (MODE == 1) v *= mul[r * 512 + cc];
            out[r * 512 + cc] = v;
        }
    }
}

// ---------------------------------------------------------------------------
// Kernel 2: scores[b,l,p] = sum_a relu(fmaps[b,p,a] + hlin[b,l,a]) * wrect[a]
// grid = (28 p-tiles of 7, 16 b) = 448 blocks, 256 threads.
// ---------------------------------------------------------------------------
__global__ __launch_bounds__(256) void scores_kernel(
    const float* __restrict__ fmaps, const float* __restrict__ wrect)
{
    const int b  = blockIdx.y;
    const int pt = blockIdx.x;           // 7-pixel tile
    __shared__ float4 fs4[PT * 128];     // 14 KB

    const float4* fbase = (const float4*)(fmaps + (size_t)(b * PP + pt * PT) * DD);
    for (int i = threadIdx.x; i < PT * 128; i += 256) fs4[i] = fbase[i];
    __syncthreads();

    const int w = threadIdx.x >> 5, lane = threadIdx.x & 31;
    float wr[4][4];
#pragma unroll
    for (int j = 0; j < 4; ++j) {
        float4 v = ((const float4*)wrect)[j * 32 + lane];
        wr[j][0] = v.x; wr[j][1] = v.y; wr[j][2] = v.z; wr[j][3] = v.w;
    }
#pragma unroll
    for (int lg = 0; lg < 4; ++lg) {
        const int l = lg * 8 + w;
        float g[4][4];
        const float4* gp = (const float4*)(g_hlin + (size_t)(b * LL + l) * AA);
#pragma unroll
        for (int j = 0; j < 4; ++j) {
            float4 v = gp[j * 32 + lane];
            g[j][0] = v.x; g[j][1] = v.y; g[j][2] = v.z; g[j][3] = v.w;
        }
#pragma unroll
        for (int p = 0; p < PT; ++p) {
            float acc = 0.f;
#pragma unroll
            for (int j = 0; j < 4; ++j) {
                float4 f = fs4[p * 128 + j * 32 + lane];
                acc = fmaf(fmaxf(f.x + g[j][0], 0.f), wr[j][0], acc);
                acc = fmaf(fmaxf(f.y + g[j][1], 0.f), wr[j][1], acc);
                acc = fmaf(fmaxf(f.z + g[j][2], 0.f), wr[j][2], acc);
                acc = fmaf(fmaxf(f.w + g[j][3], 0.f), wr[j][3], acc);
            }
#pragma unroll
            for (int o = 16; o; o >>= 1)
                acc += __shfl_xor_sync(0xffffffffu, acc, o);
            if (lane == 0)
                g_scores[(size_t)(b * LL + l) * PP + pt * PT + p] = acc;
        }
    }
}

// ---------------------------------------------------------------------------
// Kernel 3: softmax over P=196 per (b,l) row -> attnT [b][p][l] + d_out tail.
// ---------------------------------------------------------------------------
__global__ __launch_bounds__(256) void softmax_kernel(float* __restrict__ attn_out)
{
    const int row = blockIdx.x, tid = threadIdx.x;
    const int lane = tid & 31, wid = tid >> 5;
    const int b = row >> 5, l = row & 31;
    __shared__ float redm[8], reds[8];

    float v = -CUDART_INF_F;
    if (tid < PP) v = g_scores[(size_t)row * PP + tid];
    float m = v;
#pragma unroll
    for (int o = 16; o; o >>= 1) m = fmaxf(m, __shfl_xor_sync(0xffffffffu, m, o));
    if (lane == 0) redm[wid] = m;
    __syncthreads();
    float bm = redm[0];
#pragma unroll
    for (int i = 1; i < 8; ++i) bm = fmaxf(bm, redm[i]);

    float e = (tid < PP) ? __expf(v - bm) : 0.f;
    float s = e;
#pragma unroll
    for (int o = 16; o; o >>= 1) s += __shfl_xor_sync(0xffffffffu, s, o);
    if (lane == 0) reds[wid] = s;
    __syncthreads();
    float bs = 0.f;
#pragma unroll
    for (int i = 0; i < 8; ++i) bs += reds[i];
    float inv = 1.f / bs;

    if (tid < PP) {
        float a = e * inv;
        g_attnT[((size_t)b * PP + tid) * LL + l] = a;
        if (attn_out) attn_out[(size_t)row * PP + tid] = a;
    }
}

// ---------------------------------------------------------------------------
// Kernel 4a: ctx partials, single-shot blocks (no inner pipeline).
// part[pc][b,l,d] = sum_{p in 49-chunk} attnT[b,p,l] * fmap[b,p,d]
// grid = (8 d-tiles of 64, 16 b, 4 pc) = 512 blocks, 256 threads (16x16).
// Whole working set loaded up front (high MLP), ONE sync, straight FMA loop.
// ---------------------------------------------------------------------------
__global__ __launch_bounds__(256) void ctx_part_kernel(const float* __restrict__ fmaps)
{
    __shared__ __align__(16) float As[PCL][34];   // attnT chunk [p][l]  (6.7 KB)
    __shared__ __align__(16) float Bs[PCL][68];   // fmap  chunk [p][d]  (13.3 KB)

    const int tid = threadIdx.x;
    const int tx = tid & 15;         // d: 4 each
    const int ty = tid >> 4;         // l: 2 each
    const int b  = blockIdx.y;
    const int pc = blockIdx.z;
    const int dt = blockIdx.x * 64;

    const float* bg = fmaps + ((size_t)b * PP + pc * PCL) * DD + dt;
    const float* ag = g_attnT + ((size_t)b * PP + pc * PCL) * LL;

    // Interleaved fill: per step each thread issues one fmap float4 and one
    // attnT float2 LDG back-to-back (all independent -> high MLP), then all
    // the STS. 49*16 = 784 slots each, strided by 256.
    {
        const int row0 = tid >> 4;
        const int c4 = (tid & 15) * 4;
        const int c2 = (tid & 15) * 2;
#pragma unroll
        for (int s = 0; s < 4; ++s) {
            const int row = row0 + s * 16;
            if (row < PCL) {
                float4 bv = *(const float4*)&bg[(size_t)row * DD + c4];
                float2 av = *(const float2*)&ag[(size_t)row * LL + c2];
                *(float4*)&Bs[row][c4] = bv;
                *(float2*)&As[row][c2] = av;
            }
        }
    }
    __syncthreads();

    float acc[2][4];
#pragma unroll
    for (int i = 0; i < 2; ++i)
#pragma unroll
        for (int j = 0; j < 4; ++j) acc[i][j] = 0.f;

#pragma unroll 7
    for (int k = 0; k < PCL; ++k) {
        float2 a = *(const float2*)&As[k][ty * 2];
        float4 bq = *(const float4*)&Bs[k][tx * 4];
        acc[0][0] = fmaf(a.x, bq.x, acc[0][0]);
        acc[0][1] = fmaf(a.x, bq.y, acc[0][1]);
        acc[0][2] = fmaf(a.x, bq.z, acc[0][2]);
        acc[0][3] = fmaf(a.x, bq.w, acc[0][3]);
        acc[1][0] = fmaf(a.y, bq.x, acc[1][0]);
        acc[1][1] = fmaf(a.y, bq.y, acc[1][1]);
        acc[1][2] = fmaf(a.y, bq.z, acc[1][2]);
        acc[1][3] = fmaf(a.y, bq.w, acc[1][3]);
    }

#pragma unroll
    for (int i = 0; i < 2; ++i) {
        const int l = ty * 2 + i;
        *(float4*)&g_part[((size_t)pc * MM + b * LL + l) * DD + dt + tx * 4] =
            make_float4(acc[i][0], acc[i][1], acc[i][2], acc[i][3]);
    }
}

// ---------------------------------------------------------------------------
// Kernel 4b: deterministic 4-way reduce of partials -> g_ctx.
// 65536 float4 outputs; grid 256 x 256 threads.
// ---------------------------------------------------------------------------
__global__ __launch_bounds__(256) void ctx_reduce_kernel()
{
    const int i = blockIdx.x * 256 + threadIdx.x;   // float4 idx
    if (i >= MM * DD / 4) return;
    const float4* p = (const float4*)g_part;
    float4 s = p[i];
#pragma unroll
    for (int pc = 1; pc < PCN; ++pc) {
        float4 v = p[(size_t)pc * (MM * DD / 4) + i];
        s.x += v.x; s.y += v.y; s.z += v.z; s.w += v.w;
    }
    ((float4*)g_ctx)[i] = s;
}

// ---------------------------------------------------------------------------
extern "C" void kernel_launch(void* const* d_in, const int* in_sizes, int n_in,
                              void* d_out, int out_size)
{
    const float* maps     = (const float*)d_in[0];
    const float* hiddens  = (const float*)d_in[1];
    const float* W_hidden = (const float*)d_in[2];
    const float* b_hidden = (const float*)d_in[3];
    const float* W_rect   = (const float*)d_in[4];
    // d_in[5] = b_rect: softmax-invariant, unused
    const float* W_co     = (const float*)d_in[6];
    const float* b_co     = (const float*)d_in[7];

    float* out_co = (float*)d_out;
    float* out_attn = nullptr;
    if (out_size >= MM * HID + MM * PP)
        out_attn = out_co + MM * HID;

    // 1) hlin = hiddens @ W_hidden^T + b_hidden   -> g_hlin
    gemm_nt_kernel<0><<<dim3(16, 8), 256>>>(hiddens, W_hidden, b_hidden,
                                            nullptr, nullptr);
    // 2) additive co-attention scores             -> g_scores
    scores_kernel<<<dim3(28, BB), 256>>>(maps, W_rect);
    // 3) softmax over pixels                      -> g_attnT (+ d_out tail)
    softmax_kernel<<<MM, 256>>>(out_attn);
    // 4a) ctx partials (single-shot, 512 blocks)  -> g_part
    ctx_part_kernel<<<dim3(8, BB, PCN), 256>>>(maps);
    // 4b) deterministic reduce                    -> g_ctx
    ctx_reduce_kernel<<<256, 256>>>();
    // 5) co_att = (ctx @ W_co^T + b_co) * hiddens -> d_out head
    gemm_nt_kernel<1><<<dim3(16, 8), 256>>>(nullptr, W_co, b_co,
                                            hiddens, out_co);
}

// round 17
// speedup vs baseline: 1.4301x; 1.4301x over previous
#include <cuda_runtime.h>
#include <cstdint>
#include <math_constants.h>

// Problem constants
#define BB   16
#define PP   196
#define DD   512
#define LL   32
#define HID  512
#define AA   512
#define MM   (BB*LL)
#define PT   7            // pixels per scores tile
#define KC   14           // ctx k-chunk (14*14 = 196)

// ---------------- scratch (device globals; no allocation allowed) -----------
__device__ __align__(16) float g_hlin[MM * AA];
__device__ __align__(16) float g_scores[MM * PP];
__device__ __align__(16) float g_attnT[BB * PP * LL];   // [b][p][l]
__device__ __align__(16) float g_ctx[MM * DD];
__device__ __align__(16) float g_gpart[2 * MM * 512];   // split-K GEMM partials

// ---------------------------------------------------------------------------
// Split-K partial NT SGEMM: gp[s][m,n] = sum_{k in half s} X[m,k]*Wt[n,k]
//   MODE 0: X = Xp param     MODE 1: X = g_ctx
// BM=64, BN=32, BK=32, 256 threads (16x16), 8 k-chunks per block.
// K-major double-buffered smem, register-prefetch pipeline.
// grid = (16, 8, 2) = 256 blocks (~2/SM co-resident; smem 17.5 KB/block).
// ---------------------------------------------------------------------------
template<int MODE>
__global__ __launch_bounds__(256) void gemm_part_kernel(
    const float* __restrict__ Xp, const float* __restrict__ Wt)
{
    __shared__ __align__(16) float Xs[2][32][68];
    __shared__ __align__(16) float Ws[2][32][34];

    const int tid = threadIdx.x;
    const int tx = tid & 15;         // N
    const int ty = tid >> 4;         // M
    const int bm = blockIdx.y * 64;
    const int bn = blockIdx.x * 32;
    const int bz = blockIdx.z;       // k-half
    const int k0 = bz * 256;

    float acc[4][2];
#pragma unroll
    for (int i = 0; i < 4; ++i)
#pragma unroll
        for (int j = 0; j < 2; ++j) acc[i][j] = 0.f;

    const int xrow = tid >> 2;             // 0..63
    const int xko  = (tid & 3) * 4;        // 0,4,8,12 ; second vec at +16
    const int wrow = tid >> 3;             // 0..31
    const int wko  = (tid & 7) * 4;        // 0..28

    const float* X = (MODE == 0) ? Xp : g_ctx;
    const float* xg0 = X + (size_t)(bm + xrow) * 512 + k0 + xko;
    const float* wg  = Wt + (size_t)(bn + wrow) * 512 + k0 + wko;

    float4 xv0 = *(const float4*)(xg0);
    float4 xv1 = *(const float4*)(xg0 + 16);
    float4 wv  = *(const float4*)(wg);

    Xs[0][xko + 0][xrow] = xv0.x; Xs[0][xko + 1][xrow] = xv0.y;
    Xs[0][xko + 2][xrow] = xv0.z; Xs[0][xko + 3][xrow] = xv0.w;
    Xs[0][xko + 16][xrow] = xv1.x; Xs[0][xko + 17][xrow] = xv1.y;
    Xs[0][xko + 18][xrow] = xv1.z; Xs[0][xko + 19][xrow] = xv1.w;
    Ws[0][wko + 0][wrow] = wv.x; Ws[0][wko + 1][wrow] = wv.y;
    Ws[0][wko + 2][wrow] = wv.z; Ws[0][wko + 3][wrow] = wv.w;
    __syncthreads();

#pragma unroll 1
    for (int c = 0; c < 8; ++c) {
        if (c < 7) {
            const float* xg = xg0 + (c + 1) * 32;
            xv0 = *(const float4*)(xg);
            xv1 = *(const float4*)(xg + 16);
            wv  = *(const float4*)(wg + (c + 1) * 32);
        }

        const int cur = c & 1;
#pragma unroll
        for (int kk = 0; kk < 32; ++kk) {
            float4 a = *(const float4*)&Xs[cur][kk][ty * 4];
            float2 bv = *(const float2*)&Ws[cur][kk][tx * 2];
            acc[0][0] = fmaf(a.x, bv.x, acc[0][0]); acc[0][1] = fmaf(a.x, bv.y, acc[0][1]);
            acc[1][0] = fmaf(a.y, bv.x, acc[1][0]); acc[1][1] = fmaf(a.y, bv.y, acc[1][1]);
            acc[2][0] = fmaf(a.z, bv.x, acc[2][0]); acc[2][1] = fmaf(a.z, bv.y, acc[2][1]);
            acc[3][0] = fmaf(a.w, bv.x, acc[3][0]); acc[3][1] = fmaf(a.w, bv.y, acc[3][1]);
        }

        if (c < 7) {
            const int nxt = cur ^ 1;
            Xs[nxt][xko + 0][xrow] = xv0.x; Xs[nxt][xko + 1][xrow] = xv0.y;
            Xs[nxt][xko + 2][xrow] = xv0.z; Xs[nxt][xko + 3][xrow] = xv0.w;
            Xs[nxt][xko + 16][xrow] = xv1.x; Xs[nxt][xko + 17][xrow] = xv1.y;
            Xs[nxt][xko + 18][xrow] = xv1.z; Xs[nxt][xko + 19][xrow] = xv1.w;
            Ws[nxt][wko + 0][wrow] = wv.x; Ws[nxt][wko + 1][wrow] = wv.y;
            Ws[nxt][wko + 2][wrow] = wv.z; Ws[nxt][wko + 3][wrow] = wv.w;
            __syncthreads();
        }
    }

    float* out = g_gpart + (size_t)bz * (MM * 512);
#pragma unroll
    for (int i = 0; i < 4; ++i) {
        int r = bm + ty * 4 + i;
#pragma unroll
        for (int j = 0; j < 2; ++j)
            out[(size_t)r * 512 + bn + tx * 2 + j] = acc[i][j];
    }
}

// ---------------------------------------------------------------------------
// Split-K combine: out = gp0 + gp1 + bias  (MODE1: additionally * mul)
// One float4 per thread; grid 256 x 256 = 65536 float4 = MM*512 floats.
// Deterministic fixed-order sum.
// ---------------------------------------------------------------------------
template<int MODE>
__global__ __launch_bounds__(256) void gemm_combine_kernel(
    const float* __restrict__ bias, const float* __restrict__ mul,
    float* __restrict__ outp)
{
    const unsigned i = blockIdx.x * 256u + threadIdx.x;  // float4 idx < 65536
    const unsigned c4 = (i & 127u) * 4u;                 // column (float idx)
    const float4* p0 = (const float4*)g_gpart;
    const float4* p1 = p0 + (MM * 512 / 4);
    float4 a = p0[i];
    float4 b = p1[i];
    float4 bi = *(const float4*)&bias[c4];
    float4 v = make_float4(a.x + b.x + bi.x, a.y + b.y + bi.y,
                           a.z + b.z + bi.z, a.w + b.w + bi.w);
    if (MODE == 1) {
        float4 h = ((const float4*)mul)[i];
        v.x *= h.x; v.y *= h.y; v.z *= h.z; v.w *= h.w;
    }
    float* out = (MODE == 0) ? g_hlin : outp;
    ((float4*)out)[i] = v;
}

// ---------------------------------------------------------------------------
// Kernel 2: scores[b,l,p] = sum_a relu(fmaps[b,p,a] + hlin[b,l,a]) * wrect[a]
// grid = (28 p-tiles of 7, 16 b) = 448 blocks, 256 threads.
// ---------------------------------------------------------------------------
__global__ __launch_bounds__(256) void scores_kernel(
    const float* __restrict__ fmaps, const float* __restrict__ wrect)
{
    const int b  = blockIdx.y;
    const int pt = blockIdx.x;           // 7-pixel tile
    __shared__ float4 fs4[PT * 128];     // 14 KB

    const float4* fbase = (const float4*)(fmaps + (size_t)(b * PP + pt * PT) * DD);
    for (int i = threadIdx.x; i < PT * 128; i += 256) fs4[i] = fbase[i];
    __syncthreads();

    const int w = threadIdx.x >> 5, lane = threadIdx.x & 31;
    float wr[4][4];
#pragma unroll
    for (int j = 0; j < 4; ++j) {
        float4 v = ((const float4*)wrect)[j * 32 + lane];
        wr[j][0] = v.x; wr[j][1] = v.y; wr[j][2] = v.z; wr[j][3] = v.w;
    }
#pragma unroll
    for (int lg = 0; lg < 4; ++lg) {
        const int l = lg * 8 + w;
        float g[4][4];
        const float4* gp = (const float4*)(g_hlin + (size_t)(b * LL + l) * AA);
#pragma unroll
        for (int j = 0; j < 4; ++j) {
            float4 v = gp[j * 32 + lane];
            g[j][0] = v.x; g[j][1] = v.y; g[j][2] = v.z; g[j][3] = v.w;
        }
#pragma unroll
        for (int p = 0; p < PT; ++p) {
            float acc = 0.f;
#pragma unroll
            for (int j = 0; j < 4; ++j) {
                float4 f = fs4[p * 128 + j * 32 + lane];
                acc = fmaf(fmaxf(f.x + g[j][0], 0.f), wr[j][0], acc);
                acc = fmaf(fmaxf(f.y + g[j][1], 0.f), wr[j][1], acc);
                acc = fmaf(fmaxf(f.z + g[j][2], 0.f), wr[j][2], acc);
                acc = fmaf(fmaxf(f.w + g[j][3], 0.f), wr[j][3], acc);
            }
#pragma unroll
            for (int o = 16; o; o >>= 1)
                acc += __shfl_xor_sync(0xffffffffu, acc, o);
            if (lane == 0)
                g_scores[(size_t)(b * LL + l) * PP + pt * PT + p] = acc;
        }
    }
}

// ---------------------------------------------------------------------------
// Kernel 3: softmax over P=196 per (b,l) row -> attnT [b][p][l] + d_out tail.
// ---------------------------------------------------------------------------
__global__ __launch_bounds__(256) void softmax_kernel(float* __restrict__ attn_out)
{
    const int row = blockIdx.x, tid = threadIdx.x;
    const int lane = tid & 31, wid = tid >> 5;
    const int b = row >> 5, l = row & 31;
    __shared__ float redm[8], reds[8];

    float v = -CUDART_INF_F;
    if (tid < PP) v = g_scores[(size_t)row * PP + tid];
    float m = v;
#pragma unroll
    for (int o = 16; o; o >>= 1) m = fmaxf(m, __shfl_xor_sync(0xffffffffu, m, o));
    if (lane == 0) redm[wid] = m;
    __syncthreads();
    float bm = redm[0];
#pragma unroll
    for (int i = 1; i < 8; ++i) bm = fmaxf(bm, redm[i]);

    float e = (tid < PP) ? __expf(v - bm) : 0.f;
    float s = e;
#pragma unroll
    for (int o = 16; o; o >>= 1) s += __shfl_xor_sync(0xffffffffu, s, o);
    if (lane == 0) reds[wid] = s;
    __syncthreads();
    float bs = 0.f;
#pragma unroll
    for (int i = 0; i < 8; ++i) bs += reds[i];
    float inv = 1.f / bs;

    if (tid < PP) {
        float a = e * inv;
        g_attnT[((size_t)b * PP + tid) * LL + l] = a;
        if (attn_out) attn_out[(size_t)row * PP + tid] = a;
    }
}

// ---------------------------------------------------------------------------
// Kernel 4: ctx[b] (32 x 512) = attn[b] (32 x 196) @ fmap[b] (196 x 512)
// grid = (8 d-tiles of 64, 16 b) = 128 blocks, 256 threads (16x16, TM=2, TN=4).
// KC=14 k-chunks x 14, double-buffered K-major smem, register prefetch.
// (R8's proven kernel, verbatim.)
// ---------------------------------------------------------------------------
__global__ __launch_bounds__(256) void ctx_gemm_kernel(const float* __restrict__ fmaps)
{
    __shared__ __align__(16) float As[2][KC][34];   // attnT chunk [k][l]
    __shared__ __align__(16) float Bs[2][KC][68];   // fmap chunk  [k][d]

    const int tid = threadIdx.x;
    const int tx = tid & 15;         // d: 4 each
    const int ty = tid >> 4;         // l: 2 each
    const int b  = blockIdx.y;
    const int dt = blockIdx.x * 64;

    const bool ld = tid < 224;
    const int brow = tid >> 4;                 // 0..13 (tid<224)
    const int bc4  = (tid & 15) * 4;
    const int ak   = (2 * tid) >> 5;           // 0..13
    const int al   = (2 * tid) & 31;           // even

    const float* bg = fmaps + (size_t)b * PP * 512 + dt + bc4;
    const float* ag = g_attnT + (size_t)b * PP * LL;

    float4 bv; float2 av;
    if (ld) {
        bv = *(const float4*)&bg[(size_t)brow * 512];
        av = *(const float2*)&ag[(size_t)ak * LL + al];
    }
    if (ld) {
        *(float4*)&Bs[0][brow][bc4] = bv;
        *(float2*)&As[0][ak][al] = av;
    }
    __syncthreads();

    float acc[2][4];
#pragma unroll
    for (int i = 0; i < 2; ++i)
#pragma unroll
        for (int j = 0; j < 4; ++j) acc[i][j] = 0.f;

#pragma unroll 1
    for (int c = 0; c < 14; ++c) {
        if (c < 13 && ld) {
            bv = *(const float4*)&bg[(size_t)((c + 1) * KC + brow) * 512];
            av = *(const float2*)&ag[(size_t)((c + 1) * KC + ak) * LL + al];
        }
        const int cur = c & 1;
#pragma unroll
        for (int k = 0; k < KC; ++k) {
            float2 a = *(const float2*)&As[cur][k][ty * 2];
            float4 bq = *(const float4*)&Bs[cur][k][tx * 4];
            acc[0][0] = fmaf(a.x, bq.x, acc[0][0]);
            acc[0][1] = fmaf(a.x, bq.y, acc[0][1]);
            acc[0][2] = fmaf(a.x, bq.z, acc[0][2]);
            acc[0][3] = fmaf(a.x, bq.w, acc[0][3]);
            acc[1][0] = fmaf(a.y, bq.x, acc[1][0]);
            acc[1][1] = fmaf(a.y, bq.y, acc[1][1]);
            acc[1][2] = fmaf(a.y, bq.z, acc[1][2]);
            acc[1][3] = fmaf(a.y, bq.w, acc[1][3]);
        }
        if (c < 13) {
            const int nxt = cur ^ 1;
            if (ld) {
                *(float4*)&Bs[nxt][brow][bc4] = bv;
                *(float2*)&As[nxt][ak][al] = av;
            }
            __syncthreads();
        }
    }

#pragma unroll
    for (int i = 0; i < 2; ++i) {
        const int l = ty * 2 + i;
        *(float4*)&g_ctx[((size_t)b * LL + l) * 512 + dt + tx * 4] =
            make_float4(acc[i][0], acc[i][1], acc[i][2], acc[i][3]);
    }
}

// ---------------------------------------------------------------------------
extern "C" void kernel_launch(void* const* d_in, const int* in_sizes, int n_in,
                              void* d_out, int out_size)
{
    const float* maps     = (const float*)d_in[0];
    const float* hiddens  = (const float*)d_in[1];
    const float* W_hidden = (const float*)d_in[2];
    const float* b_hidden = (const float*)d_in[3];
    const float* W_rect   = (const float*)d_in[4];
    // d_in[5] = b_rect: softmax-invariant, unused
    const float* W_co     = (const float*)d_in[6];
    const float* b_co     = (const float*)d_in[7];

    float* out_co = (float*)d_out;
    float* out_attn = nullptr;
    if (out_size >= MM * HID + MM * PP)
        out_attn = out_co + MM * HID;

    // 1) hlin = hiddens @ W_hidden^T + b_hidden  (split-K=2)
    gemm_part_kernel<0><<<dim3(16, 8, 2), 256>>>(hiddens, W_hidden);
    gemm_combine_kernel<0><<<256, 256>>>(b_hidden, nullptr, nullptr);
    // 2) additive co-attention scores             -> g_scores
    scores_kernel<<<dim3(28, BB), 256>>>(maps, W_rect);
    // 3) softmax over pixels                      -> g_attnT (+ d_out tail)
    softmax_kernel<<<MM, 256>>>(out_attn);
    // 4) ctx = attn @ fmaps (per-batch GEMM)      -> g_ctx
    ctx_gemm_kernel<<<dim3(8, BB), 256>>>(maps);
    // 5) co_att = (ctx @ W_co^T + b_co) * hiddens (split-K=2)
    gemm_part_kernel<1><<<dim3(16, 8, 2), 256>>>(nullptr, W_co);
    gemm_combine_kernel<1><<<256, 256>>>(b_co, hiddens, out_co);
}